// round 9
// baseline (speedup 1.0000x reference)
#include <cuda_runtime.h>
#include <cuda_fp16.h>
#include <cstdint>

#define C 128
#define MAXN 100000
#define MAXE 1600000
#define LN_EPS 1e-5f

// Scratch (allocation-free rule: __device__ globals; BSS zero-initialized.
// Invariants at kernel_launch entry (restored every replay):
//   g_cursor all-zero (k_agg tail re-zeros), g_scanstate zeroed by k_detect.)
__device__ __half    g_hh[MAXN * 128];     // h fp16 [N,128]
__device__ __half    g_meanh[MAXN * 128];  // mean fp16 [N,128]
__device__ int       g_rowstart[MAXN + 1]; // CSR row offsets (by dst)
__device__ int       g_cursor[MAXN];       // counts -> offsets -> fill cursor
__device__ int       g_csr[MAXE];          // src ids grouped by dst
__device__ unsigned  g_scanstate[128];     // per-chunk published totals (+1)
__device__ int       g_is64;               // edge_index dtype flag

// ===========================================================================
// K0: detect edge_index dtype (single block) + zero scan states
// ===========================================================================
__global__ void k_detect(const void* ei_, int N, int E) {
    if (threadIdx.x < 128) g_scanstate[threadIdx.x] = 0u;
    const long long* p = (const long long*)ei_;
    int n = E < 1024 ? E : 1024;
    bool ok = true;
    for (int j = threadIdx.x; j < n; j += blockDim.x) {
        long long v = p[j];
        if (v < 0 || v >= (long long)N) ok = false;
    }
    ok = __syncthreads_and(ok);
    if (threadIdx.x == 0) g_is64 = ok ? 1 : 0;
}

__device__ __forceinline__ int load_edge(const void* ei_, size_t idx) {
    if (g_is64) return (int)((const long long*)ei_)[idx];
    return ((const int*)ei_)[idx];
}

// ===========================================================================
// K1: MERGED LayerNorm+ReLU (blocks [0, lnblocks)) and dst-degree histogram
// ===========================================================================
__global__ void k_ln_hist(const float* __restrict__ x,
                          const float* __restrict__ gamma,
                          const float* __restrict__ beta,
                          const void* ei_, int N, int E, int lnblocks) {
    if ((int)blockIdx.x < lnblocks) {
        int w    = (blockIdx.x * blockDim.x + threadIdx.x) >> 5;
        int lane = threadIdx.x & 31;
        if (w >= N) return;

        float4 v = ((const float4*)x)[(size_t)w * 32 + lane];
        float s  = v.x + v.y + v.z + v.w;
        float sq = v.x * v.x + v.y * v.y + v.z * v.z + v.w * v.w;
#pragma unroll
        for (int o = 16; o; o >>= 1) {
            s  += __shfl_xor_sync(0xffffffffu, s, o);
            sq += __shfl_xor_sync(0xffffffffu, sq, o);
        }
        float mu  = s * (1.0f / C);
        float var = sq * (1.0f / C) - mu * mu;
        float rs  = rsqrtf(var + LN_EPS);

        float4 g = ((const float4*)gamma)[lane];
        float4 b = ((const float4*)beta)[lane];
        float hx = fmaxf(0.0f, (v.x - mu) * rs * g.x + b.x);
        float hy = fmaxf(0.0f, (v.y - mu) * rs * g.y + b.y);
        float hz = fmaxf(0.0f, (v.z - mu) * rs * g.z + b.z);
        float hw = fmaxf(0.0f, (v.w - mu) * rs * g.w + b.w);

        __half2 p0 = __floats2half2_rn(hx, hy);
        __half2 p1 = __floats2half2_rn(hz, hw);
        uint2 pk = make_uint2(*(uint32_t*)&p0, *(uint32_t*)&p1);
        ((uint2*)g_hh)[(size_t)w * 32 + lane] = pk;
    } else {
        int e = (blockIdx.x - lnblocks) * blockDim.x + threadIdx.x;
        if (e >= E) return;
        int d = load_edge(ei_, (size_t)E + e);
        atomicAdd(&g_cursor[d], 1);
    }
}

// ===========================================================================
// K2: single-pass exclusive scan (publish chunk total, gather predecessors).
// All nb<=128 blocks co-resident (nb=98 < 148 SMs) => spin-gather is safe.
// ===========================================================================
__global__ void k_scan(int N, int nb) {
    __shared__ int wsum[8];
    __shared__ int s_ex;
    int b = blockIdx.x, t = threadIdx.x;
    int lane = t & 31, wid = t >> 5;
    int idx0 = b * 1024 + t * 4;

    int c[4];
#pragma unroll
    for (int k = 0; k < 4; ++k)
        c[k] = (idx0 + k < N) ? g_cursor[idx0 + k] : 0;
    int tsum = c[0] + c[1] + c[2] + c[3];

    int v = tsum;
#pragma unroll
    for (int o = 1; o < 32; o <<= 1) {
        int xx = __shfl_up_sync(0xffffffffu, v, o);
        if (lane >= o) v += xx;
    }
    if (lane == 31) wsum[wid] = v;
    __syncthreads();

    // thread 0: warp-sums -> exclusive, publish block total (+1; 0 = empty)
    if (t == 0) {
        int run = 0;
#pragma unroll
        for (int i = 0; i < 8; ++i) { int w = wsum[i]; wsum[i] = run; run += w; }
        atomicExch(&g_scanstate[b], (unsigned)(run + 1));
    }
    __syncthreads();

    // warp 0: gather exclusive prefix over predecessor blocks
    if (wid == 0) {
        int ex = 0;
        for (int w0 = 0; w0 < b; w0 += 32) {
            int j = w0 + lane;
            int val = 0;
            if (j < b) {
                unsigned st;
                while ((st = atomicAdd(&g_scanstate[j], 0u)) == 0u)
                    __nanosleep(64);
                val = (int)st - 1;
            }
#pragma unroll
            for (int o = 16; o; o >>= 1)
                val += __shfl_xor_sync(0xffffffffu, val, o);
            ex += val;
        }
        if (lane == 0) s_ex = ex;
    }
    __syncthreads();

    int texcl = (v - tsum) + wsum[wid];
    int run = s_ex + texcl;
#pragma unroll
    for (int k = 0; k < 4; ++k) {
        int idx = idx0 + k;
        if (idx < N) {
            g_rowstart[idx] = run;
            g_cursor[idx]   = run;
            run += c[k];
            if (idx == N - 1) g_rowstart[N] = run;
        }
    }
}

// ===========================================================================
// K3: fill CSR src lists (4 edges per thread, vectorized loads)
// ===========================================================================
__global__ void k_fill(const void* ei_, int N, int E) {
    int e0 = (blockIdx.x * blockDim.x + threadIdx.x) * 4;
    if (e0 >= E) return;
    int s[4], d[4];
    int m = E - e0; if (m > 4) m = 4;
    if (g_is64) {
        const long long* ei = (const long long*)ei_;
        if (m == 4) {
            longlong2 sa = *(const longlong2*)(ei + e0);
            longlong2 sb = *(const longlong2*)(ei + e0 + 2);
            longlong2 da = *(const longlong2*)(ei + E + e0);
            longlong2 db = *(const longlong2*)(ei + E + e0 + 2);
            s[0]=(int)sa.x; s[1]=(int)sa.y; s[2]=(int)sb.x; s[3]=(int)sb.y;
            d[0]=(int)da.x; d[1]=(int)da.y; d[2]=(int)db.x; d[3]=(int)db.y;
        } else {
            for (int k = 0; k < m; ++k) {
                s[k] = (int)ei[e0 + k];
                d[k] = (int)ei[(size_t)E + e0 + k];
            }
        }
    } else {
        const int* ei = (const int*)ei_;
        if (m == 4) {
            int4 sa = *(const int4*)(ei + e0);
            int4 da = *(const int4*)(ei + E + e0);
            s[0]=sa.x; s[1]=sa.y; s[2]=sa.z; s[3]=sa.w;
            d[0]=da.x; d[1]=da.y; d[2]=da.z; d[3]=da.w;
        } else {
            for (int k = 0; k < m; ++k) {
                s[k] = ei[e0 + k];
                d[k] = ei[(size_t)E + e0 + k];
            }
        }
    }
#pragma unroll
    for (int k = 0; k < 4; ++k) {
        if (k < m) {
            int pos = atomicAdd(&g_cursor[d[k]], 1);
            g_csr[pos] = s[k];
        }
    }
}

// ===========================================================================
// K4: gather-sum aggregation, one warp per dst node; 2 neighbor rows per
// step (lanes 0-15 even neighbor, 16-31 odd), uint4 (16B) loads.
// Tail: re-zero g_cursor to restore the entry invariant for the next replay.
// ===========================================================================
__global__ void k_agg(int N) {
    int w    = (blockIdx.x * blockDim.x + threadIdx.x) >> 5;
    int lane = threadIdx.x & 31;
    if (w >= N) return;

    int start = g_rowstart[w];
    int end   = g_rowstart[w + 1];
    int deg   = end - start;

    int half = lane >> 4;     // 0: even-index neighbor, 1: odd
    int cl   = lane & 15;     // 8-channel group within the row

    float acc[8];
#pragma unroll
    for (int i = 0; i < 8; ++i) acc[i] = 0.f;

    const uint4* hh = (const uint4*)g_hh;
    for (int base = start; base < end; base += 32) {
        int m = end - base; if (m > 32) m = 32;
        int s = (lane < m) ? g_csr[base + lane] : 0;
#pragma unroll 4
        for (int j = 0; j < 32; j += 2) {
            if (j >= m) break;
            int r0 = __shfl_sync(0xffffffffu, s, j);
            int r1 = __shfl_sync(0xffffffffu, s, j + 1);
            int row = half ? r1 : r0;
            bool ok = half ? (j + 1 < m) : true;
            if (ok) {
                uint4 pk = hh[(size_t)row * 16 + cl];
                float2 f0 = __half22float2(*(__half2*)&pk.x);
                float2 f1 = __half22float2(*(__half2*)&pk.y);
                float2 f2 = __half22float2(*(__half2*)&pk.z);
                float2 f3 = __half22float2(*(__half2*)&pk.w);
                acc[0] += f0.x; acc[1] += f0.y;
                acc[2] += f1.x; acc[3] += f1.y;
                acc[4] += f2.x; acc[5] += f2.y;
                acc[6] += f3.x; acc[7] += f3.y;
            }
        }
    }

    // combine odd-half accumulators into even half (same channels)
#pragma unroll
    for (int i = 0; i < 8; ++i)
        acc[i] += __shfl_down_sync(0xffffffffu, acc[i], 16);

    if (half == 0) {
        float inv = deg > 0 ? 1.0f / (float)deg : 0.0f;
        __half2 p0 = __floats2half2_rn(acc[0] * inv, acc[1] * inv);
        __half2 p1 = __floats2half2_rn(acc[2] * inv, acc[3] * inv);
        __half2 p2 = __floats2half2_rn(acc[4] * inv, acc[5] * inv);
        __half2 p3 = __floats2half2_rn(acc[6] * inv, acc[7] * inv);
        uint4 pk;
        pk.x = *(uint32_t*)&p0; pk.y = *(uint32_t*)&p1;
        pk.z = *(uint32_t*)&p2; pk.w = *(uint32_t*)&p3;
        ((uint4*)g_meanh)[(size_t)w * 16 + cl] = pk;
    }
    if (lane == 0) g_cursor[w] = 0;   // restore invariant for next replay
}

// ===========================================================================
// tf32 helpers (mma.sync path — plain sm_103-compatible PTX)
// ===========================================================================
__device__ __forceinline__ uint32_t to_tf32(float f) {
    uint32_t r;
    asm("cvt.rna.tf32.f32 %0, %1;" : "=r"(r) : "f"(f));
    return r;
}

__device__ __forceinline__ void mma_tf32(float4& d,
                                         uint32_t a0, uint32_t a1,
                                         uint32_t a2, uint32_t a3,
                                         uint32_t b0, uint32_t b1) {
    asm volatile(
        "mma.sync.aligned.m16n8k8.row.col.f32.tf32.tf32.f32 "
        "{%0,%1,%2,%3}, {%4,%5,%6,%7}, {%8,%9}, {%0,%1,%2,%3};"
        : "+f"(d.x), "+f"(d.y), "+f"(d.z), "+f"(d.w)
        : "r"(a0), "r"(a1), "r"(a2), "r"(a3), "r"(b0), "r"(b1));
}

// ===========================================================================
// K5: tensor-core GEMM epilogue via mma.sync m16n8k8 tf32.
//   out[128-row tile, 128] = mean @ Wl^T + h @ Wr^T + bias + x
// ===========================================================================
#define BPITCH 260
#define APITCH 132
#define OFF_B  0
#define OFF_A  (128 * BPITCH)             // floats
#define OFF_BI (OFF_A + 128 * APITCH)     // floats
#define SMEM_FLOATS (OFF_BI + 128)
#define SMEM_TOT (SMEM_FLOATS * 4)

__global__ void __launch_bounds__(256, 1)
k_gemm_mma(const float* __restrict__ x,
           const float* __restrict__ Wl,
           const float* __restrict__ bl,
           const float* __restrict__ Wr,
           float* __restrict__ out, int N, int ntiles) {
    extern __shared__ float smem[];
    float* sB  = smem + OFF_B;
    float* sA  = smem + OFF_A;
    float* sbi = smem + OFF_BI;

    int tid  = threadIdx.x;
    int wid  = tid >> 5;
    int lane = tid & 31;
    int ly   = lane >> 2;   // groupID 0..7
    int lx   = lane & 3;    // threadID_in_group 0..3

    // Stage B (tf32-rounded), coalesced reads, contiguous SMEM writes.
    for (int i = tid; i < 128 * 128; i += 256) {
        int n = i >> 7, k = i & 127;
        sB[n * BPITCH + k]       = __uint_as_float(to_tf32(Wl[i]));
        sB[n * BPITCH + 128 + k] = __uint_as_float(to_tf32(Wr[i]));
    }
    for (int i = tid; i < 128; i += 256) sbi[i] = bl[i];
    __syncthreads();

    const uint4* meanp = (const uint4*)g_meanh;  // 8 halves per uint4, 16/row
    const uint4* hp    = (const uint4*)g_hh;
    const uint32_t* sAu = (const uint32_t*)sA;
    const uint32_t* sBu = (const uint32_t*)sB;

    int rb = wid * 16;   // warp's row block within the tile

    for (int t = blockIdx.x; t < ntiles; t += gridDim.x) {
        int rbase = t * 128;
        float4 acc[16];
#pragma unroll
        for (int nt = 0; nt < 16; ++nt) acc[nt] = make_float4(0.f, 0.f, 0.f, 0.f);

#pragma unroll
        for (int half = 0; half < 2; ++half) {
            // stage A half (mean for half 0, h for half 1) from fp16
            const uint4* src = half ? hp : meanp;
            for (int i = tid; i < 128 * 16; i += 256) {
                int r = i >> 4, c8 = i & 15;     // c8: 8-half group
                int row = rbase + r;
                float4 w0, w1;
                if (row < N) {
                    uint4 pk = src[(size_t)row * 16 + c8];
                    float2 f0 = __half22float2(*(__half2*)&pk.x);
                    float2 f1 = __half22float2(*(__half2*)&pk.y);
                    float2 f2 = __half22float2(*(__half2*)&pk.z);
                    float2 f3 = __half22float2(*(__half2*)&pk.w);
                    w0 = make_float4(f0.x, f0.y, f1.x, f1.y);
                    w1 = make_float4(f2.x, f2.y, f3.x, f3.y);
                } else {
                    w0 = make_float4(0.f, 0.f, 0.f, 0.f);
                    w1 = w0;
                }
                *(float4*)(sA + r * APITCH + c8 * 8)     = w0;
                *(float4*)(sA + r * APITCH + c8 * 8 + 4) = w1;
            }
            __syncthreads();

            int kbase = half * 128;   // B column offset for this half
#pragma unroll
            for (int ks = 0; ks < 16; ++ks) {
                int kl = ks * 8;
                uint32_t a0 = sAu[(rb + ly)     * APITCH + kl + lx];
                uint32_t a1 = sAu[(rb + ly + 8) * APITCH + kl + lx];
                uint32_t a2 = sAu[(rb + ly)     * APITCH + kl + lx + 4];
                uint32_t a3 = sAu[(rb + ly + 8) * APITCH + kl + lx + 4];
#pragma unroll
                for (int nt = 0; nt < 16; ++nt) {
                    uint32_t b0 = sBu[(nt * 8 + ly) * BPITCH + kbase + kl + lx];
                    uint32_t b1 = sBu[(nt * 8 + ly) * BPITCH + kbase + kl + lx + 4];
                    mma_tf32(acc[nt], a0, a1, a2, a3, b0, b1);
                }
            }
            __syncthreads();   // acc lives in regs; sA can be restaged
        }

        // Epilogue: c0,c1 -> (row ly, cols 2lx,2lx+1); c2,c3 -> row ly+8
        int row0 = rbase + rb + ly;
        int row1 = row0 + 8;
#pragma unroll
        for (int nt = 0; nt < 16; ++nt) {
            int col = nt * 8 + lx * 2;
            float2 bv = *(const float2*)(sbi + col);
            if (row0 < N) {
                float2 xv = ((const float2*)x)[(size_t)row0 * 64 + (col >> 1)];
                float2 o = make_float2(acc[nt].x + bv.x + xv.x,
                                       acc[nt].y + bv.y + xv.y);
                ((float2*)out)[(size_t)row0 * 64 + (col >> 1)] = o;
            }
            if (row1 < N) {
                float2 xv = ((const float2*)x)[(size_t)row1 * 64 + (col >> 1)];
                float2 o = make_float2(acc[nt].z + bv.x + xv.x,
                                       acc[nt].w + bv.y + xv.y);
                ((float2*)out)[(size_t)row1 * 64 + (col >> 1)] = o;
            }
        }
    }
}

// ===========================================================================
extern "C" void kernel_launch(void* const* d_in, const int* in_sizes, int n_in,
                              void* d_out, int out_size) {
    const float* x     = (const float*)d_in[0];
    const void*  ei    = d_in[1];
    const float* gamma = (const float*)d_in[2];
    const float* beta  = (const float*)d_in[3];
    const float* Wl    = (const float*)d_in[4];
    const float* bl    = (const float*)d_in[5];
    const float* Wr    = (const float*)d_in[6];
    float*       out   = (float*)d_out;

    int N = in_sizes[0] / C;       // 100000
    int E = in_sizes[1] / 2;       // 1600000
    int nb = (N + 1023) / 1024;    // 98 — co-resident, single-pass scan OK
    int ntiles = (N + 127) / 128;

    int lnblocks   = (N + 7) / 8;            // 12500
    int histblocks = (E + 255) / 256;        // 6250

    k_detect<<<1, 256>>>(ei, N, E);                                        // 0
    k_ln_hist<<<lnblocks + histblocks, 256>>>(x, gamma, beta, ei, N, E, lnblocks); // 1
    k_scan<<<nb, 256>>>(N, nb);                                            // 2
    k_fill<<<(E / 4 + 255) / 256, 256>>>(ei, N, E);                        // 3 <- profiled
    k_agg<<<(N + 7) / 8, 256>>>(N);                                        // 4

    cudaFuncSetAttribute(k_gemm_mma, cudaFuncAttributeMaxDynamicSharedMemorySize,
                         SMEM_TOT);
    int sms = 148;
    cudaDeviceGetAttribute(&sms, cudaDevAttrMultiProcessorCount, 0);
    int grid = sms < ntiles ? sms : ntiles;
    k_gemm_mma<<<grid, 256, SMEM_TOT>>>(x, Wl, bl, Wr, out, N, ntiles);    // 5
}

// round 10
// speedup vs baseline: 1.1719x; 1.1719x over previous
#include <cuda_runtime.h>
#include <cuda_fp16.h>
#include <cstdint>

#define C 128
#define MAXN 100000
#define MAXE 1600000
#define LN_EPS 1e-5f

// Scratch (allocation-free rule: __device__ globals; BSS zero-initialized.
// Invariant: g_cursor all-zero at kernel_launch entry — guaranteed at load
// and re-established by k_agg's tail on every invocation.)
__device__ __half g_hh[MAXN * 128];     // h = relu(layernorm(x)), fp16 [N,128]
__device__ __half g_meanh[MAXN * 128];  // mean of neighbor messages, fp16 [N,128]
__device__ int    g_rowstart[MAXN + 1]; // CSR row offsets (by dst)
__device__ int    g_cursor[MAXN];       // counts -> offsets -> fill cursor
__device__ int    g_csr[MAXE];          // src ids grouped by dst
__device__ int    g_blocksums[256];
__device__ int    g_is64;               // edge_index dtype flag

// ===========================================================================
// K0: detect edge_index dtype (single block)
// ===========================================================================
__global__ void k_detect(const void* ei_, int N, int E) {
    const long long* p = (const long long*)ei_;
    int n = E < 1024 ? E : 1024;
    bool ok = true;
    for (int j = threadIdx.x; j < n; j += blockDim.x) {
        long long v = p[j];
        if (v < 0 || v >= (long long)N) ok = false;
    }
    ok = __syncthreads_and(ok);
    if (threadIdx.x == 0) g_is64 = ok ? 1 : 0;
}

__device__ __forceinline__ int load_edge(const void* ei_, size_t idx) {
    if (g_is64) return (int)((const long long*)ei_)[idx];
    return ((const int*)ei_)[idx];
}

// ===========================================================================
// K1: MERGED LayerNorm+ReLU (blocks [0, lnblocks)) and dst-degree histogram
// ===========================================================================
__global__ void k_ln_hist(const float* __restrict__ x,
                          const float* __restrict__ gamma,
                          const float* __restrict__ beta,
                          const void* ei_, int N, int E, int lnblocks) {
    if ((int)blockIdx.x < lnblocks) {
        int w    = (blockIdx.x * blockDim.x + threadIdx.x) >> 5;
        int lane = threadIdx.x & 31;
        if (w >= N) return;

        float4 v = ((const float4*)x)[(size_t)w * 32 + lane];
        float s  = v.x + v.y + v.z + v.w;
        float sq = v.x * v.x + v.y * v.y + v.z * v.z + v.w * v.w;
#pragma unroll
        for (int o = 16; o; o >>= 1) {
            s  += __shfl_xor_sync(0xffffffffu, s, o);
            sq += __shfl_xor_sync(0xffffffffu, sq, o);
        }
        float mu  = s * (1.0f / C);
        float var = sq * (1.0f / C) - mu * mu;
        float rs  = rsqrtf(var + LN_EPS);

        float4 g = ((const float4*)gamma)[lane];
        float4 b = ((const float4*)beta)[lane];
        float hx = fmaxf(0.0f, (v.x - mu) * rs * g.x + b.x);
        float hy = fmaxf(0.0f, (v.y - mu) * rs * g.y + b.y);
        float hz = fmaxf(0.0f, (v.z - mu) * rs * g.z + b.z);
        float hw = fmaxf(0.0f, (v.w - mu) * rs * g.w + b.w);

        __half2 p0 = __floats2half2_rn(hx, hy);
        __half2 p1 = __floats2half2_rn(hz, hw);
        uint2 pk = make_uint2(*(uint32_t*)&p0, *(uint32_t*)&p1);
        ((uint2*)g_hh)[(size_t)w * 32 + lane] = pk;
    } else {
        int e = (blockIdx.x - lnblocks) * blockDim.x + threadIdx.x;
        if (e >= E) return;
        int d = load_edge(ei_, (size_t)E + e);
        atomicAdd(&g_cursor[d], 1);
    }
}

// ===========================================================================
// K2: scan phase 1 — per-1024-chunk sums
// ===========================================================================
__global__ void k_scan1(int N) {
    __shared__ int sh[8];
    int b = blockIdx.x, t = threadIdx.x;
    int base = b * 1024;
    int sum = 0;
    for (int i = t; i < 1024; i += 256) {
        int idx = base + i;
        if (idx < N) sum += g_cursor[idx];
    }
#pragma unroll
    for (int o = 16; o; o >>= 1) sum += __shfl_xor_sync(0xffffffffu, sum, o);
    if ((t & 31) == 0) sh[t >> 5] = sum;
    __syncthreads();
    if (t == 0) {
        int tot = 0;
#pragma unroll
        for (int i = 0; i < 8; ++i) tot += sh[i];
        g_blocksums[b] = tot;
    }
}

// ===========================================================================
// K3: scan phase 2 — in-block blocksum prefix + local scan -> rowstart/cursor
// ===========================================================================
__global__ void k_scan3(int N, int nb) {
    __shared__ int wsum[8];
    __shared__ int ssum[8];
    int b = blockIdx.x, t = threadIdx.x;
    int lane = t & 31, wid = t >> 5;

    int bs = (t < nb && t < b) ? g_blocksums[t] : 0;
#pragma unroll
    for (int o = 16; o; o >>= 1) bs += __shfl_xor_sync(0xffffffffu, bs, o);
    if (lane == 0) ssum[wid] = bs;
    __syncthreads();
    int block_off = 0;
#pragma unroll
    for (int i = 0; i < 8; ++i) block_off += ssum[i];

    int idx0 = b * 1024 + t * 4;
    int c[4];
#pragma unroll
    for (int k = 0; k < 4; ++k)
        c[k] = (idx0 + k < N) ? g_cursor[idx0 + k] : 0;
    int tsum = c[0] + c[1] + c[2] + c[3];

    int v = tsum;
#pragma unroll
    for (int o = 1; o < 32; o <<= 1) {
        int xx = __shfl_up_sync(0xffffffffu, v, o);
        if (lane >= o) v += xx;
    }
    if (lane == 31) wsum[wid] = v;
    __syncthreads();
    if (t == 0) {
        int run = 0;
#pragma unroll
        for (int i = 0; i < 8; ++i) { int w = wsum[i]; wsum[i] = run; run += w; }
    }
    __syncthreads();

    int texcl = (v - tsum) + wsum[wid];
    int run = block_off + texcl;
#pragma unroll
    for (int k = 0; k < 4; ++k) {
        int idx = idx0 + k;
        if (idx < N) {
            g_rowstart[idx] = run;
            g_cursor[idx]   = run;
            run += c[k];
            if (idx == N - 1) g_rowstart[N] = run;
        }
    }
}

// ===========================================================================
// K4: fill CSR src lists (2 edges per thread, vectorized loads)
// ===========================================================================
__global__ void k_fill(const void* ei_, int N, int E) {
    int e0 = (blockIdx.x * blockDim.x + threadIdx.x) * 2;
    if (e0 >= E) return;
    if (g_is64) {
        const long long* ei = (const long long*)ei_;
        if (e0 + 1 < E) {
            longlong2 sp = *(const longlong2*)(ei + e0);
            longlong2 dp = *(const longlong2*)(ei + E + e0);
            int p0 = atomicAdd(&g_cursor[(int)dp.x], 1);
            int p1 = atomicAdd(&g_cursor[(int)dp.y], 1);
            g_csr[p0] = (int)sp.x;
            g_csr[p1] = (int)sp.y;
        } else {
            int s = (int)ei[e0], d = (int)ei[(size_t)E + e0];
            g_csr[atomicAdd(&g_cursor[d], 1)] = s;
        }
    } else {
        const int* ei = (const int*)ei_;
        if (e0 + 1 < E) {
            int2 sp = *(const int2*)(ei + e0);
            int2 dp = *(const int2*)(ei + E + e0);
            int p0 = atomicAdd(&g_cursor[dp.x], 1);
            int p1 = atomicAdd(&g_cursor[dp.y], 1);
            g_csr[p0] = sp.x;
            g_csr[p1] = sp.y;
        } else {
            int s = ei[e0], d = ei[(size_t)E + e0];
            g_csr[atomicAdd(&g_cursor[d], 1)] = s;
        }
    }
}

// ===========================================================================
// K5: gather-sum aggregation, one warp per dst node (full occupancy).
// Tail: re-zero g_cursor to restore the entry invariant for the next replay.
// ===========================================================================
__global__ void k_agg(int N) {
    int w    = (blockIdx.x * blockDim.x + threadIdx.x) >> 5;
    int lane = threadIdx.x & 31;
    if (w >= N) return;

    int start = g_rowstart[w];
    int end   = g_rowstart[w + 1];
    int deg   = end - start;

    float4 acc = make_float4(0.f, 0.f, 0.f, 0.f);
    const uint2* hh = (const uint2*)g_hh;
    for (int base = start; base < end; base += 32) {
        int m = end - base; if (m > 32) m = 32;
        int s = (lane < m) ? g_csr[base + lane] : 0;
#pragma unroll 8
        for (int j = 0; j < 32; ++j) {
            if (j >= m) break;
            int sj = __shfl_sync(0xffffffffu, s, j);
            uint2 pk = hh[(size_t)sj * 32 + lane];
            float2 f0 = __half22float2(*(__half2*)&pk.x);
            float2 f1 = __half22float2(*(__half2*)&pk.y);
            acc.x += f0.x; acc.y += f0.y; acc.z += f1.x; acc.w += f1.y;
        }
    }
    float inv = deg > 0 ? 1.0f / (float)deg : 0.0f;
    __half2 p0 = __floats2half2_rn(acc.x * inv, acc.y * inv);
    __half2 p1 = __floats2half2_rn(acc.z * inv, acc.w * inv);
    ((uint2*)g_meanh)[(size_t)w * 32 + lane] =
        make_uint2(*(uint32_t*)&p0, *(uint32_t*)&p1);

    if (lane == 0) g_cursor[w] = 0;   // restore invariant for next replay
}

// ===========================================================================
// fp16 mma helper (m16n8k16, fp32 accumulate — plain sm_103 PTX, sm_80+)
// ===========================================================================
__device__ __forceinline__ void mma_f16(float4& d,
                                        uint32_t a0, uint32_t a1,
                                        uint32_t a2, uint32_t a3,
                                        uint32_t b0, uint32_t b1) {
    asm volatile(
        "mma.sync.aligned.m16n8k16.row.col.f32.f16.f16.f32 "
        "{%0,%1,%2,%3}, {%4,%5,%6,%7}, {%8,%9}, {%0,%1,%2,%3};"
        : "+f"(d.x), "+f"(d.y), "+f"(d.z), "+f"(d.w)
        : "r"(a0), "r"(a1), "r"(a2), "r"(a3), "r"(b0), "r"(b1));
}

// ===========================================================================
// K6: fp16 tensor-core GEMM epilogue via mma.sync m16n8k16.
//   out[128-row tile, 128] = mean @ Wl^T + h @ Wr^T + bias + x
// SMEM (halves):
//   sB: [128 n][264 pitch]  B[n][k] = Wl[n][k] (k<128) | Wr[n][k-128], fp16
//       (row-major [n][k] == col-major KxN as mma.row.col expects)
//   sA: [128 r][136 pitch]  current A half, raw fp16 copy (no conversion)
//   bias fp32 [128]
// Frag-load banks: 4*ly+lx (pitches 264/136 halves = 4 banks/row mod 32)
// -> conflict-free. ~103KB total -> 2 CTAs/SM.
// ===========================================================================
#define BPITCH_H 264
#define APITCH_H 136
#define OFFH_B   0
#define OFFH_A   (128 * BPITCH_H)               // halves
#define OFFH_BI  (OFFH_A + 128 * APITCH_H)      // halves (bias as fp32 after)
#define SMEM_HALVES (OFFH_BI + 256)             // 256 halves = 128 floats
#define SMEM_TOT (SMEM_HALVES * 2)

__global__ void __launch_bounds__(256, 2)
k_gemm_mma(const float* __restrict__ x,
           const float* __restrict__ Wl,
           const float* __restrict__ bl,
           const float* __restrict__ Wr,
           float* __restrict__ out, int N, int ntiles) {
    extern __shared__ __half smemh[];
    __half* sB  = smemh + OFFH_B;
    __half* sA  = smemh + OFFH_A;
    float*  sbi = (float*)(smemh + OFFH_BI);

    int tid  = threadIdx.x;
    int wid  = tid >> 5;
    int lane = tid & 31;
    int ly   = lane >> 2;   // groupID 0..7
    int lx   = lane & 3;    // threadID_in_group 0..3

    // Stage B (fp16), coalesced fp32 reads.
    for (int i = tid; i < 128 * 128; i += 256) {
        int n = i >> 7, k = i & 127;
        sB[n * BPITCH_H + k]       = __float2half(Wl[i]);
        sB[n * BPITCH_H + 128 + k] = __float2half(Wr[i]);
    }
    for (int i = tid; i < 128; i += 256) sbi[i] = bl[i];
    __syncthreads();

    const uint4* meanp = (const uint4*)g_meanh;  // 8 halves per uint4, 16/row
    const uint4* hp    = (const uint4*)g_hh;
    const uint32_t* sAu = (const uint32_t*)sA;   // index in 4B units (2 halves)
    const uint32_t* sBu = (const uint32_t*)sB;
    uint4* sA4 = (uint4*)sA;                     // APITCH_H/8 = 17 uint4 per row

    int rb = wid * 16;   // warp's row block within the tile

    for (int t = blockIdx.x; t < ntiles; t += gridDim.x) {
        int rbase = t * 128;
        float4 acc[16];
#pragma unroll
        for (int nt = 0; nt < 16; ++nt) acc[nt] = make_float4(0.f, 0.f, 0.f, 0.f);

#pragma unroll
        for (int half = 0; half < 2; ++half) {
            // stage A half (mean for half 0, h for half 1): raw fp16 copy
            const uint4* src = half ? hp : meanp;
            for (int i = tid; i < 128 * 16; i += 256) {
                int r = i >> 4, c8 = i & 15;     // c8: 8-half group
                int row = rbase + r;
                uint4 pk = (row < N) ? src[(size_t)row * 16 + c8]
                                     : make_uint4(0u, 0u, 0u, 0u);
                sA4[r * 17 + c8] = pk;
            }
            __syncthreads();

            int kbase2 = half * 64;   // B k-offset in 4B units (128 halves)
#pragma unroll
            for (int ks = 0; ks < 8; ++ks) {
                int kl2 = ks * 8;     // k-step offset in 4B units (16 halves)
                // A frags: rows rb+ly / rb+ly+8, half-pairs (2lx), (2lx+8)
                uint32_t a0 = sAu[(rb + ly)     * (APITCH_H / 2) + kl2 + lx];
                uint32_t a1 = sAu[(rb + ly + 8) * (APITCH_H / 2) + kl2 + lx];
                uint32_t a2 = sAu[(rb + ly)     * (APITCH_H / 2) + kl2 + lx + 4];
                uint32_t a3 = sAu[(rb + ly + 8) * (APITCH_H / 2) + kl2 + lx + 4];
#pragma unroll
                for (int nt = 0; nt < 16; ++nt) {
                    int nrow = nt * 8 + ly;
                    uint32_t b0 = sBu[nrow * (BPITCH_H / 2) + kbase2 + kl2 + lx];
                    uint32_t b1 = sBu[nrow * (BPITCH_H / 2) + kbase2 + kl2 + lx + 4];
                    mma_f16(acc[nt], a0, a1, a2, a3, b0, b1);
                }
            }
            __syncthreads();   // acc lives in regs; sA can be restaged
        }

        // Epilogue: c0,c1 -> (row ly, cols 2lx,2lx+1); c2,c3 -> row ly+8
        int row0 = rbase + rb + ly;
        int row1 = row0 + 8;
#pragma unroll
        for (int nt = 0; nt < 16; ++nt) {
            int col = nt * 8 + lx * 2;
            float2 bv = *(const float2*)(sbi + col);
            if (row0 < N) {
                float2 xv = ((const float2*)x)[(size_t)row0 * 64 + (col >> 1)];
                float2 o = make_float2(acc[nt].x + bv.x + xv.x,
                                       acc[nt].y + bv.y + xv.y);
                ((float2*)out)[(size_t)row0 * 64 + (col >> 1)] = o;
            }
            if (row1 < N) {
                float2 xv = ((const float2*)x)[(size_t)row1 * 64 + (col >> 1)];
                float2 o = make_float2(acc[nt].z + bv.x + xv.x,
                                       acc[nt].w + bv.y + xv.y);
                ((float2*)out)[(size_t)row1 * 64 + (col >> 1)] = o;
            }
        }
    }
}

// ===========================================================================
extern "C" void kernel_launch(void* const* d_in, const int* in_sizes, int n_in,
                              void* d_out, int out_size) {
    const float* x     = (const float*)d_in[0];
    const void*  ei    = d_in[1];
    const float* gamma = (const float*)d_in[2];
    const float* beta  = (const float*)d_in[3];
    const float* Wl    = (const float*)d_in[4];
    const float* bl    = (const float*)d_in[5];
    const float* Wr    = (const float*)d_in[6];
    float*       out   = (float*)d_out;

    int N = in_sizes[0] / C;       // 100000
    int E = in_sizes[1] / 2;       // 1600000
    int nb = (N + 1023) / 1024;    // 98
    int ntiles = (N + 127) / 128;

    int lnblocks   = (N + 7) / 8;            // 12500
    int histblocks = (E + 255) / 256;        // 6250

    k_detect<<<1, 256>>>(ei, N, E);
    k_ln_hist<<<lnblocks + histblocks, 256>>>(x, gamma, beta, ei, N, E, lnblocks);
    k_scan1<<<nb, 256>>>(N);
    k_scan3<<<nb, 256>>>(N, nb);
    k_fill<<<(E / 2 + 255) / 256, 256>>>(ei, N, E);
    k_agg<<<(N + 7) / 8, 256>>>(N);

    cudaFuncSetAttribute(k_gemm_mma, cudaFuncAttributeMaxDynamicSharedMemorySize,
                         SMEM_TOT);
    int sms = 148;
    cudaDeviceGetAttribute(&sms, cudaDevAttrMultiProcessorCount, 0);
    int grid = 2 * sms < ntiles ? 2 * sms : ntiles;
    k_gemm_mma<<<grid, 256, SMEM_TOT>>>(x, Wl, bl, Wr, out, N, ntiles);
}

// round 11
// speedup vs baseline: 1.1762x; 1.0036x over previous
#include <cuda_runtime.h>
#include <cuda_fp16.h>
#include <cstdint>

#define C 128
#define MAXN 100000
#define MAXE 1600000
#define LN_EPS 1e-5f

// Scratch (allocation-free rule: __device__ globals; BSS zero-initialized.
// Invariants at kernel_launch entry (restored every replay):
//   g_cursor all-zero   (k_agg tail re-zeros)
//   g_scanstate all-zero (ln_hist block 0 re-zeros; graph-ordered before scan)
__device__ __half    g_hh[MAXN * 128];     // h fp16 [N,128]
__device__ __half    g_meanh[MAXN * 128];  // mean fp16 [N,128]
__device__ int       g_rowstart[MAXN + 1]; // CSR row offsets (by dst)
__device__ int       g_cursor[MAXN];       // counts -> offsets -> fill cursor
__device__ int       g_csr[MAXE];          // src ids grouped by dst
__device__ unsigned  g_scanstate[128];     // per-chunk published totals (+1)

// ===========================================================================
// Inline edge-dtype detection: 32 int64 samples all in [0,N) => int64.
// (int32 data misreads as hi*2^32+lo with hi a ~U[0,1e5) node id; all-32
//  hi==0 has P ~ 1e-160.) Warp-uniform result, 1 cached LDG + ballot.
// ===========================================================================
__device__ __forceinline__ bool is_i64(const void* ei_, int N, int E) {
    int lane = threadIdx.x & 31;
    int n = E < 32 ? E : 32;
    long long v = ((const long long*)ei_)[lane % n];
    bool ok = (v >= 0 && v < (long long)N);
    return __all_sync(0xffffffffu, ok);
}

// ===========================================================================
// K0: MERGED LayerNorm+ReLU (blocks [0, lnblocks)) and dst-degree histogram.
// Block 0 also re-zeros g_scanstate for this replay's scan.
// ===========================================================================
__global__ void k_ln_hist(const float* __restrict__ x,
                          const float* __restrict__ gamma,
                          const float* __restrict__ beta,
                          const void* ei_, int N, int E, int lnblocks) {
    if (blockIdx.x == 0 && threadIdx.x < 128) g_scanstate[threadIdx.x] = 0u;

    if ((int)blockIdx.x < lnblocks) {
        int w    = (blockIdx.x * blockDim.x + threadIdx.x) >> 5;
        int lane = threadIdx.x & 31;
        if (w >= N) return;

        float4 v = ((const float4*)x)[(size_t)w * 32 + lane];
        float s  = v.x + v.y + v.z + v.w;
        float sq = v.x * v.x + v.y * v.y + v.z * v.z + v.w * v.w;
#pragma unroll
        for (int o = 16; o; o >>= 1) {
            s  += __shfl_xor_sync(0xffffffffu, s, o);
            sq += __shfl_xor_sync(0xffffffffu, sq, o);
        }
        float mu  = s * (1.0f / C);
        float var = sq * (1.0f / C) - mu * mu;
        float rs  = rsqrtf(var + LN_EPS);

        float4 g = ((const float4*)gamma)[lane];
        float4 b = ((const float4*)beta)[lane];
        float hx = fmaxf(0.0f, (v.x - mu) * rs * g.x + b.x);
        float hy = fmaxf(0.0f, (v.y - mu) * rs * g.y + b.y);
        float hz = fmaxf(0.0f, (v.z - mu) * rs * g.z + b.z);
        float hw = fmaxf(0.0f, (v.w - mu) * rs * g.w + b.w);

        __half2 p0 = __floats2half2_rn(hx, hy);
        __half2 p1 = __floats2half2_rn(hz, hw);
        uint2 pk = make_uint2(*(uint32_t*)&p0, *(uint32_t*)&p1);
        ((uint2*)g_hh)[(size_t)w * 32 + lane] = pk;
    } else {
        bool i64 = is_i64(ei_, N, E);
        int e = (blockIdx.x - lnblocks) * blockDim.x + threadIdx.x;
        if (e >= E) return;
        int d = i64 ? (int)((const long long*)ei_)[(size_t)E + e]
                    : ((const int*)ei_)[(size_t)E + e];
        atomicAdd(&g_cursor[d], 1);
    }
}

// ===========================================================================
// K1: single-pass exclusive scan (publish chunk total, gather predecessors).
// All nb<=128 blocks co-resident (nb=98 < 148 SMs) => spin-gather is safe.
// ===========================================================================
__global__ void k_scan(int N, int nb) {
    __shared__ int wsum[8];
    __shared__ int s_ex;
    int b = blockIdx.x, t = threadIdx.x;
    int lane = t & 31, wid = t >> 5;
    int idx0 = b * 1024 + t * 4;

    int c[4];
#pragma unroll
    for (int k = 0; k < 4; ++k)
        c[k] = (idx0 + k < N) ? g_cursor[idx0 + k] : 0;
    int tsum = c[0] + c[1] + c[2] + c[3];

    int v = tsum;
#pragma unroll
    for (int o = 1; o < 32; o <<= 1) {
        int xx = __shfl_up_sync(0xffffffffu, v, o);
        if (lane >= o) v += xx;
    }
    if (lane == 31) wsum[wid] = v;
    __syncthreads();

    if (t == 0) {
        int run = 0;
#pragma unroll
        for (int i = 0; i < 8; ++i) { int w = wsum[i]; wsum[i] = run; run += w; }
        atomicExch(&g_scanstate[b], (unsigned)(run + 1));  // publish (+1)
    }
    __syncthreads();

    if (wid == 0) {
        int ex = 0;
        for (int w0 = 0; w0 < b; w0 += 32) {
            int j = w0 + lane;
            int val = 0;
            if (j < b) {
                unsigned st;
                while ((st = atomicAdd(&g_scanstate[j], 0u)) == 0u)
                    __nanosleep(64);
                val = (int)st - 1;
            }
#pragma unroll
            for (int o = 16; o; o >>= 1)
                val += __shfl_xor_sync(0xffffffffu, val, o);
            ex += val;
        }
        if (lane == 0) s_ex = ex;
    }
    __syncthreads();

    int texcl = (v - tsum) + wsum[wid];
    int run = s_ex + texcl;
#pragma unroll
    for (int k = 0; k < 4; ++k) {
        int idx = idx0 + k;
        if (idx < N) {
            g_rowstart[idx] = run;
            g_cursor[idx]   = run;
            run += c[k];
            if (idx == N - 1) g_rowstart[N] = run;
        }
    }
}

// ===========================================================================
// K2: fill CSR src lists (2 edges per thread, vectorized loads)
// ===========================================================================
__global__ void k_fill(const void* ei_, int N, int E) {
    bool i64 = is_i64(ei_, N, E);
    int e0 = (blockIdx.x * blockDim.x + threadIdx.x) * 2;
    if (e0 >= E) return;
    if (i64) {
        const long long* ei = (const long long*)ei_;
        if (e0 + 1 < E) {
            longlong2 sp = *(const longlong2*)(ei + e0);
            longlong2 dp = *(const longlong2*)(ei + E + e0);
            int p0 = atomicAdd(&g_cursor[(int)dp.x], 1);
            int p1 = atomicAdd(&g_cursor[(int)dp.y], 1);
            g_csr[p0] = (int)sp.x;
            g_csr[p1] = (int)sp.y;
        } else {
            int s = (int)ei[e0], d = (int)ei[(size_t)E + e0];
            g_csr[atomicAdd(&g_cursor[d], 1)] = s;
        }
    } else {
        const int* ei = (const int*)ei_;
        if (e0 + 1 < E) {
            int2 sp = *(const int2*)(ei + e0);
            int2 dp = *(const int2*)(ei + E + e0);
            int p0 = atomicAdd(&g_cursor[dp.x], 1);
            int p1 = atomicAdd(&g_cursor[dp.y], 1);
            g_csr[p0] = sp.x;
            g_csr[p1] = sp.y;
        } else {
            int s = ei[e0], d = ei[(size_t)E + e0];
            g_csr[atomicAdd(&g_cursor[d], 1)] = s;
        }
    }
}

// ===========================================================================
// K3: gather-sum aggregation, one warp per dst node (full occupancy).
// Tail: re-zero g_cursor to restore the entry invariant for the next replay.
// ===========================================================================
__global__ void k_agg(int N) {
    int w    = (blockIdx.x * blockDim.x + threadIdx.x) >> 5;
    int lane = threadIdx.x & 31;
    if (w >= N) return;

    int start = g_rowstart[w];
    int end   = g_rowstart[w + 1];
    int deg   = end - start;

    float4 acc = make_float4(0.f, 0.f, 0.f, 0.f);
    const uint2* hh = (const uint2*)g_hh;
    for (int base = start; base < end; base += 32) {
        int m = end - base; if (m > 32) m = 32;
        int s = (lane < m) ? g_csr[base + lane] : 0;
#pragma unroll 8
        for (int j = 0; j < 32; ++j) {
            if (j >= m) break;
            int sj = __shfl_sync(0xffffffffu, s, j);
            uint2 pk = hh[(size_t)sj * 32 + lane];
            float2 f0 = __half22float2(*(__half2*)&pk.x);
            float2 f1 = __half22float2(*(__half2*)&pk.y);
            acc.x += f0.x; acc.y += f0.y; acc.z += f1.x; acc.w += f1.y;
        }
    }
    float inv = deg > 0 ? 1.0f / (float)deg : 0.0f;
    __half2 p0 = __floats2half2_rn(acc.x * inv, acc.y * inv);
    __half2 p1 = __floats2half2_rn(acc.z * inv, acc.w * inv);
    ((uint2*)g_meanh)[(size_t)w * 32 + lane] =
        make_uint2(*(uint32_t*)&p0, *(uint32_t*)&p1);

    if (lane == 0) g_cursor[w] = 0;   // restore invariant for next replay
}

// ===========================================================================
// fp16 mma helper (m16n8k16, fp32 accumulate — plain sm_103 PTX, sm_80+)
// ===========================================================================
__device__ __forceinline__ void mma_f16(float4& d,
                                        uint32_t a0, uint32_t a1,
                                        uint32_t a2, uint32_t a3,
                                        uint32_t b0, uint32_t b1) {
    asm volatile(
        "mma.sync.aligned.m16n8k16.row.col.f32.f16.f16.f32 "
        "{%0,%1,%2,%3}, {%4,%5,%6,%7}, {%8,%9}, {%0,%1,%2,%3};"
        : "+f"(d.x), "+f"(d.y), "+f"(d.z), "+f"(d.w)
        : "r"(a0), "r"(a1), "r"(a2), "r"(a3), "r"(b0), "r"(b1));
}

// ===========================================================================
// K4: fp16 tensor-core GEMM epilogue via mma.sync m16n8k16.
//   out[128-row tile, 128] = mean @ Wl^T + h @ Wr^T + bias + x
// ~103KB SMEM -> 2 CTAs/SM.
// ===========================================================================
#define BPITCH_H 264
#define APITCH_H 136
#define OFFH_B   0
#define OFFH_A   (128 * BPITCH_H)               // halves
#define OFFH_BI  (OFFH_A + 128 * APITCH_H)      // halves (bias fp32 region)
#define SMEM_HALVES (OFFH_BI + 256)
#define SMEM_TOT (SMEM_HALVES * 2)

__global__ void __launch_bounds__(256, 2)
k_gemm_mma(const float* __restrict__ x,
           const float* __restrict__ Wl,
           const float* __restrict__ bl,
           const float* __restrict__ Wr,
           float* __restrict__ out, int N, int ntiles) {
    extern __shared__ __half smemh[];
    __half* sB  = smemh + OFFH_B;
    __half* sA  = smemh + OFFH_A;
    float*  sbi = (float*)(smemh + OFFH_BI);

    int tid  = threadIdx.x;
    int wid  = tid >> 5;
    int lane = tid & 31;
    int ly   = lane >> 2;   // groupID 0..7
    int lx   = lane & 3;    // threadID_in_group 0..3

    for (int i = tid; i < 128 * 128; i += 256) {
        int n = i >> 7, k = i & 127;
        sB[n * BPITCH_H + k]       = __float2half(Wl[i]);
        sB[n * BPITCH_H + 128 + k] = __float2half(Wr[i]);
    }
    for (int i = tid; i < 128; i += 256) sbi[i] = bl[i];
    __syncthreads();

    const uint4* meanp = (const uint4*)g_meanh;
    const uint4* hp    = (const uint4*)g_hh;
    const uint32_t* sAu = (const uint32_t*)sA;
    const uint32_t* sBu = (const uint32_t*)sB;
    uint4* sA4 = (uint4*)sA;

    int rb = wid * 16;

    for (int t = blockIdx.x; t < ntiles; t += gridDim.x) {
        int rbase = t * 128;
        float4 acc[16];
#pragma unroll
        for (int nt = 0; nt < 16; ++nt) acc[nt] = make_float4(0.f, 0.f, 0.f, 0.f);

#pragma unroll
        for (int half = 0; half < 2; ++half) {
            const uint4* src = half ? hp : meanp;
            for (int i = tid; i < 128 * 16; i += 256) {
                int r = i >> 4, c8 = i & 15;
                int row = rbase + r;
                uint4 pk = (row < N) ? src[(size_t)row * 16 + c8]
                                     : make_uint4(0u, 0u, 0u, 0u);
                sA4[r * 17 + c8] = pk;
            }
            __syncthreads();

            int kbase2 = half * 64;
#pragma unroll
            for (int ks = 0; ks < 8; ++ks) {
                int kl2 = ks * 8;
                uint32_t a0 = sAu[(rb + ly)     * (APITCH_H / 2) + kl2 + lx];
                uint32_t a1 = sAu[(rb + ly + 8) * (APITCH_H / 2) + kl2 + lx];
                uint32_t a2 = sAu[(rb + ly)     * (APITCH_H / 2) + kl2 + lx + 4];
                uint32_t a3 = sAu[(rb + ly + 8) * (APITCH_H / 2) + kl2 + lx + 4];
#pragma unroll
                for (int nt = 0; nt < 16; ++nt) {
                    int nrow = nt * 8 + ly;
                    uint32_t b0 = sBu[nrow * (BPITCH_H / 2) + kbase2 + kl2 + lx];
                    uint32_t b1 = sBu[nrow * (BPITCH_H / 2) + kbase2 + kl2 + lx + 4];
                    mma_f16(acc[nt], a0, a1, a2, a3, b0, b1);
                }
            }
            __syncthreads();
        }

        int row0 = rbase + rb + ly;
        int row1 = row0 + 8;
#pragma unroll
        for (int nt = 0; nt < 16; ++nt) {
            int col = nt * 8 + lx * 2;
            float2 bv = *(const float2*)(sbi + col);
            if (row0 < N) {
                float2 xv = ((const float2*)x)[(size_t)row0 * 64 + (col >> 1)];
                float2 o = make_float2(acc[nt].x + bv.x + xv.x,
                                       acc[nt].y + bv.y + xv.y);
                ((float2*)out)[(size_t)row0 * 64 + (col >> 1)] = o;
            }
            if (row1 < N) {
                float2 xv = ((const float2*)x)[(size_t)row1 * 64 + (col >> 1)];
                float2 o = make_float2(acc[nt].z + bv.x + xv.x,
                                       acc[nt].w + bv.y + xv.y);
                ((float2*)out)[(size_t)row1 * 64 + (col >> 1)] = o;
            }
        }
    }
}

// ===========================================================================
extern "C" void kernel_launch(void* const* d_in, const int* in_sizes, int n_in,
                              void* d_out, int out_size) {
    const float* x     = (const float*)d_in[0];
    const void*  ei    = d_in[1];
    const float* gamma = (const float*)d_in[2];
    const float* beta  = (const float*)d_in[3];
    const float* Wl    = (const float*)d_in[4];
    const float* bl    = (const float*)d_in[5];
    const float* Wr    = (const float*)d_in[6];
    float*       out   = (float*)d_out;

    int N = in_sizes[0] / C;       // 100000
    int E = in_sizes[1] / 2;       // 1600000
    int nb = (N + 1023) / 1024;    // 98 — co-resident, single-pass scan OK
    int ntiles = (N + 127) / 128;

    int lnblocks   = (N + 7) / 8;            // 12500
    int histblocks = (E + 255) / 256;        // 6250

    k_ln_hist<<<lnblocks + histblocks, 256>>>(x, gamma, beta, ei, N, E, lnblocks); // 0
    k_scan<<<nb, 256>>>(N, nb);                                                    // 1
    k_fill<<<(E / 2 + 255) / 256, 256>>>(ei, N, E);                                // 2
    k_agg<<<(N + 7) / 8, 256>>>(N);                                                // 3 <- profiled
    cudaFuncSetAttribute(k_gemm_mma, cudaFuncAttributeMaxDynamicSharedMemorySize,
                         SMEM_TOT);
    int sms = 148;
    cudaDeviceGetAttribute(&sms, cudaDevAttrMultiProcessorCount, 0);
    int grid = 2 * sms < ntiles ? 2 * sms : ntiles;
    k_gemm_mma<<<grid, 256, SMEM_TOT>>>(x, Wl, bl, Wr, out, N, ntiles);            // 4
}